// round 7
// baseline (speedup 1.0000x reference)
#include <cuda_runtime.h>
#include <stdint.h>
#include <stddef.h>

// ---------------------------------------------------------------------------
// JAX PRNG: partitionable threefry (validated: rel_err 1.8e-7)
// ---------------------------------------------------------------------------

#define NROWS_MAX 100000
#define NEDGE_MAX 1200000

struct U2 { uint32_t x, y; };
struct __align__(8) Edge { int col; float val; };

// ------------------------------ threefry2x32 -------------------------------
static __host__ __device__ __forceinline__ uint32_t rotl32(uint32_t x, uint32_t r) {
#ifdef __CUDA_ARCH__
    return __funnelshift_l(x, x, r);
#else
    return (x << r) | (x >> (32u - r));
#endif
}

static __host__ __device__ __forceinline__ U2 threefry2x32(uint32_t k0, uint32_t k1,
                                                           uint32_t x0, uint32_t x1) {
    uint32_t k2 = k0 ^ k1 ^ 0x1BD11BDAu;
    x0 += k0; x1 += k1;
#define TF_R(r) { x0 += x1; x1 = rotl32(x1, r); x1 ^= x0; }
    TF_R(13) TF_R(15) TF_R(26) TF_R(6)   x0 += k1; x1 += k2 + 1u;
    TF_R(17) TF_R(29) TF_R(16) TF_R(24)  x0 += k2; x1 += k0 + 2u;
    TF_R(13) TF_R(15) TF_R(26) TF_R(6)   x0 += k0; x1 += k1 + 3u;
    TF_R(17) TF_R(29) TF_R(16) TF_R(24)  x0 += k1; x1 += k2 + 4u;
    TF_R(13) TF_R(15) TF_R(26) TF_R(6)   x0 += k2; x1 += k0 + 5u;
#undef TF_R
    U2 r; r.x = x0; r.y = x1; return r;
}

// keep (u < 0.9): exact integer form of  bitcast(0x3f800000|bits>>9)-1 < 0.9f
static __device__ __forceinline__ bool keep_90(uint32_t k0, uint32_t k1, uint32_t idx) {
    U2 o = threefry2x32(k0, k1, 0u, idx);
    return (((o.x ^ o.y) >> 9)) < 0x00733333u;
}

// ------------------------------ device scratch -----------------------------
// INVARIANT: g_cnt is all-zero at the start of every kernel_launch call.
// (Zero-initialized at module load; k_scan re-zeroes it after consuming it.)
__device__ int      g_cnt[NROWS_MAX];
__device__ int      g_rowptr[NROWS_MAX];
__device__ int      g_rowend[NROWS_MAX];
__device__ int      g_cursor[NROWS_MAX];
__device__ uint32_t g_keep[(NEDGE_MAX + 31) / 32];
__device__ int      g_eid[NEDGE_MAX];
__device__ Edge     g_edges[NEDGE_MAX];
__device__ float    g_egoA[(size_t)NROWS_MAX * 64];
__device__ float    g_egoB[(size_t)NROWS_MAX * 64];

// ------------------------------ CSR build ----------------------------------
__global__ void k_hist(const int* __restrict__ rows, int E,
                       uint32_t k0, uint32_t k1) {
    int e = blockIdx.x * blockDim.x + threadIdx.x;
    bool keep = (e < E) && keep_90(k0, k1, (uint32_t)e);
    uint32_t m = __ballot_sync(0xffffffffu, keep);
    if ((e & 31) == 0 && e < E) g_keep[e >> 5] = m;
    if (keep) atomicAdd(&g_cnt[rows[e]], 1);
}

// fused exclusive scan (single block); re-zeroes g_cnt (keeps invariant)
__global__ void __launch_bounds__(1024) k_scan(int n) {
    __shared__ int warpsum[32];
    int t = threadIdx.x;
    int per = (n + 1023) >> 10;
    int s = t * per;
    int e = s + per; if (e > n) e = n;
    if (s > n) s = n;

    int sum = 0;
    for (int i = s; i < e; i++) sum += g_cnt[i];

    int lane = t & 31, wid = t >> 5;
    int v = sum;
    #pragma unroll
    for (int o = 1; o < 32; o <<= 1) {
        int u = __shfl_up_sync(0xffffffffu, v, o);
        if (lane >= o) v += u;
    }
    if (lane == 31) warpsum[wid] = v;
    __syncthreads();
    if (wid == 0) {
        int w = warpsum[lane];
        #pragma unroll
        for (int o = 1; o < 32; o <<= 1) {
            int u = __shfl_up_sync(0xffffffffu, w, o);
            if (lane >= o) w += u;
        }
        warpsum[lane] = w;
    }
    __syncthreads();

    int run = (v - sum) + (wid > 0 ? warpsum[wid - 1] : 0);
    for (int i = s; i < e; i++) {
        int c = g_cnt[i];
        g_rowptr[i] = run;
        g_cursor[i] = run;
        g_rowend[i] = run + c;
        g_cnt[i]    = 0;
        run += c;
    }
}

__global__ void k_scatter(const int* __restrict__ rows, int E) {
    int e = blockIdx.x * blockDim.x + threadIdx.x;
    if (e >= E) return;
    if ((g_keep[e >> 5] >> (e & 31)) & 1u) {
        int p = atomicAdd(&g_cursor[rows[e]], 1);
        g_eid[p] = e;
    }
}

// ------------------------------ fused layer kernel -------------------------
#define LB_THREADS 256
#define LB_ROWS    64
#define SCR_W      68   // side row width in floats (also int sort scratch)

__global__ void __launch_bounds__(LB_THREADS, 5)
k_layer(int srcSel,                       // 0 = emb param, 1 = egoA, 2 = egoB
        const float4* __restrict__ embIn,
        int dstSel,                       // 1 = egoA, 2 = egoB
        const float* __restrict__ W, const float* __restrict__ b,
        float4* __restrict__ out4,        // out as float4, row stride 64
        int layer,
        uint32_t k0, uint32_t k1,
        int copyEmb, int buildEdges,
        const int* __restrict__ cols, const float* __restrict__ vals,
        int n)
{
    __shared__ __align__(16) float4 Ws[64 * 16];
    __shared__ __align__(16) float  side[LB_ROWS][SCR_W];
    __shared__ __align__(16) float  bs[64];

    const float2* ego2 = (srcSel == 0) ? (const float2*)embIn
                        : (srcSel == 1) ? (const float2*)g_egoA : (const float2*)g_egoB;
    float4* egoOut = (dstSel == 1) ? (float4*)g_egoA : (float4*)g_egoB;

    int tid = threadIdx.x;

    const float4* W4 = (const float4*)W;
    for (int i = tid; i < 1024; i += LB_THREADS) Ws[i] = W4[i];
    if (tid < 16) ((float4*)bs)[tid] = ((const float4*)b)[tid];

    // ---- layer 0 only: per-row ascending-eid sort in SMEM scratch, then
    //      materialize g_edges (reused by layers 1 and 2) -------------------
    if (buildEdges) {
        int* scr = (int*)&side[0][0];
        if (tid < LB_ROWS) {
            int r = blockIdx.x * LB_ROWS + tid;
            if (r < n) {
                int s = g_rowptr[r], t = g_rowend[r];
                int deg = t - s;
                int* rowscr = scr + tid * SCR_W;
                if (deg <= SCR_W) {
                    for (int i = 0; i < deg; i++) rowscr[i] = g_eid[s + i];
                    for (int i = 1; i < deg; i++) {
                        int key = rowscr[i], j = i - 1;
                        while (j >= 0 && rowscr[j] > key) { rowscr[j + 1] = rowscr[j]; j--; }
                        rowscr[j + 1] = key;
                    }
                } else {  // effectively unreachable (max deg ~32)
                    for (int i = s + 1; i < t; i++) {
                        int key = g_eid[i], j = i - 1;
                        while (j >= s && g_eid[j] > key) { g_eid[j + 1] = g_eid[j]; j--; }
                        g_eid[j + 1] = key;
                    }
                }
            }
        }
        __syncthreads();
        {
            int lr = tid >> 2, l4 = tid & 3;
            int r = blockIdx.x * LB_ROWS + lr;
            if (r < n) {
                int s = g_rowptr[r];
                int deg = g_rowend[r] - s;
                const int* rowscr = scr + lr * SCR_W;
                if (deg <= SCR_W) {
                    for (int i = l4; i < deg; i += 4) {
                        int e = rowscr[i];
                        Edge ed; ed.col = cols[e]; ed.val = vals[e] * (1.0f / 0.9f);
                        g_edges[s + i] = ed;
                    }
                } else {
                    for (int i = l4; i < deg; i += 4) {
                        int e = g_eid[s + i];
                        Edge ed; ed.col = cols[e]; ed.val = vals[e] * (1.0f / 0.9f);
                        g_edges[s + i] = ed;
                    }
                }
            }
        }
        __syncthreads();
    }

    // -------- SpMM phase: WARP-PER-ROW. Each lane owns cols {2l, 2l+1}. ----
    // Warp w handles local rows w*8 .. w*8+7 sequentially. One LDG.64 per
    // edge covers the source row contiguously (256B) -> ~3 L1 wavefronts/edge
    // instead of ~32, and zero intra-warp divergence.
    {
        int wrp  = tid >> 5;
        int lane = tid & 31;
        #pragma unroll
        for (int m = 0; m < 8; m++) {
            int lr = wrp * 8 + m;
            int r  = blockIdx.x * LB_ROWS + lr;
            float2 acc = make_float2(0.f, 0.f);
            if (r < n) {
                int e   = g_rowptr[r];
                int end = g_rowend[r];
                for (; e + 3 < end; e += 4) {
                    Edge e0 = g_edges[e];
                    Edge e1 = g_edges[e + 1];
                    Edge e2 = g_edges[e + 2];
                    Edge e3 = g_edges[e + 3];
                    float2 x0 = __ldg(ego2 + (((size_t)e0.col) << 5) + lane);
                    float2 x1 = __ldg(ego2 + (((size_t)e1.col) << 5) + lane);
                    float2 x2 = __ldg(ego2 + (((size_t)e2.col) << 5) + lane);
                    float2 x3 = __ldg(ego2 + (((size_t)e3.col) << 5) + lane);
                    acc.x = fmaf(e0.val, x0.x, acc.x); acc.y = fmaf(e0.val, x0.y, acc.y);
                    acc.x = fmaf(e1.val, x1.x, acc.x); acc.y = fmaf(e1.val, x1.y, acc.y);
                    acc.x = fmaf(e2.val, x2.x, acc.x); acc.y = fmaf(e2.val, x2.y, acc.y);
                    acc.x = fmaf(e3.val, x3.x, acc.x); acc.y = fmaf(e3.val, x3.y, acc.y);
                }
                for (; e < end; e++) {
                    Edge e0 = g_edges[e];
                    float2 x0 = __ldg(ego2 + (((size_t)e0.col) << 5) + lane);
                    acc.x = fmaf(e0.val, x0.x, acc.x); acc.y = fmaf(e0.val, x0.y, acc.y);
                }
            }
            *(float2*)&side[lr][lane * 2] = acc;
        }
    }
    __syncthreads();

    // -------- GEMM phase: thread = 4 cols (cg) x 4 rows (rq) ----------------
    int cg = tid & 15;
    int rq = tid >> 4;
    int rbase = blockIdx.x * LB_ROWS + rq * 4;

    float4 h[4];
    float4 bb = ((const float4*)bs)[cg];
    #pragma unroll
    for (int m = 0; m < 4; m++) h[m] = bb;

    #pragma unroll 16
    for (int k = 0; k < 64; k++) {
        float4 w = Ws[k * 16 + cg];
        #pragma unroll
        for (int m = 0; m < 4; m++) {
            float s = side[rq * 4 + m][k];
            h[m].x = fmaf(s, w.x, h[m].x);
            h[m].y = fmaf(s, w.y, h[m].y);
            h[m].z = fmaf(s, w.z, h[m].z);
            h[m].w = fmaf(s, w.w, h[m].w);
        }
    }

    // -------- dropout + write ego_next + row-normalize + write out ----------
    #pragma unroll
    for (int m = 0; m < 4; m++) {
        int row = rbase + m;
        uint32_t base = (uint32_t)row * 64u + (uint32_t)cg * 4u;
        float4 hm = h[m];
        hm.x = keep_90(k0, k1, base + 0u) ? hm.x * (1.0f / 0.9f) : 0.0f;
        hm.y = keep_90(k0, k1, base + 1u) ? hm.y * (1.0f / 0.9f) : 0.0f;
        hm.z = keep_90(k0, k1, base + 2u) ? hm.z * (1.0f / 0.9f) : 0.0f;
        hm.w = keep_90(k0, k1, base + 3u) ? hm.w * (1.0f / 0.9f) : 0.0f;

        float ss = hm.x * hm.x + hm.y * hm.y + hm.z * hm.z + hm.w * hm.w;
        #pragma unroll
        for (int msk = 1; msk <= 8; msk <<= 1)
            ss += __shfl_xor_sync(0xffffffffu, ss, msk);

        float nrm  = sqrtf(ss);
        float invn = 1.0f / fmaxf(nrm, 1e-12f);

        if (row < n) {
            egoOut[(size_t)row * 16 + cg] = hm;
            float4 o;
            o.x = hm.x * invn; o.y = hm.y * invn;
            o.z = hm.z * invn; o.w = hm.w * invn;
            out4[(size_t)row * 64 + (size_t)(layer + 1) * 16 + cg] = o;
            if (copyEmb)
                out4[(size_t)row * 64 + cg] = embIn[(size_t)row * 16 + cg];
        }
    }
}

// ------------------------------ host entry ---------------------------------
extern "C" void kernel_launch(void* const* d_in, const int* in_sizes, int n_in,
                              void* d_out, int out_size) {
    const int*   rows = (const int*)d_in[0];
    const int*   cols = (const int*)d_in[1];
    const float* vals = (const float*)d_in[2];
    const float* emb  = (const float*)d_in[3];
    const float* W0   = (const float*)d_in[4];
    const float* b0   = (const float*)d_in[5];
    const float* W1   = (const float*)d_in[6];
    const float* b1   = (const float*)d_in[7];
    const float* W2   = (const float*)d_in[8];
    const float* b2   = (const float*)d_in[9];

    int E = in_sizes[0];
    int N = in_sizes[3] / 64;
    if (E > NEDGE_MAX) E = NEDGE_MAX;
    if (N > NROWS_MAX) N = NROWS_MAX;
    float* out = (float*)d_out;

    // subkeys of jax.random.key(42) -> split(.,4): [k_node, k0, k1, k2]
    U2 kn = threefry2x32(0u, 42u, 0u, 0u);
    U2 kA = threefry2x32(0u, 42u, 0u, 1u);
    U2 kB = threefry2x32(0u, 42u, 0u, 2u);
    U2 kC = threefry2x32(0u, 42u, 0u, 3u);

    int tb = 256;
    // launches: [0]=hist [1]=scan [2]=scatter [3]=layer0 <- ncu  [4]=L1 [5]=L2
    k_hist   <<<(E + tb - 1) / tb, tb>>>(rows, E, kn.x, kn.y);
    k_scan   <<<1, 1024>>>(N);
    k_scatter<<<(E + tb - 1) / tb, tb>>>(rows, E);

    int gb = (N + LB_ROWS - 1) / LB_ROWS;
    k_layer<<<gb, LB_THREADS>>>(0, (const float4*)emb, 1, W0, b0,
                                (float4*)out, 0, kA.x, kA.y, 1, 1, cols, vals, N);
    k_layer<<<gb, LB_THREADS>>>(1, (const float4*)emb, 2, W1, b1,
                                (float4*)out, 1, kB.x, kB.y, 0, 0, cols, vals, N);
    k_layer<<<gb, LB_THREADS>>>(2, (const float4*)emb, 1, W2, b2,
                                (float4*)out, 2, kC.x, kC.y, 0, 0, cols, vals, N);
}

// round 8
// speedup vs baseline: 2.1895x; 2.1895x over previous
#include <cuda_runtime.h>
#include <stdint.h>
#include <stddef.h>

// ---------------------------------------------------------------------------
// JAX PRNG: partitionable threefry (validated: rel_err 1.8e-7)
// ---------------------------------------------------------------------------

#define NROWS_MAX 100000
#define NEDGE_MAX 1200000

struct U2 { uint32_t x, y; };
struct __align__(8) Edge { int col; float val; };

// ------------------------------ threefry2x32 -------------------------------
static __host__ __device__ __forceinline__ uint32_t rotl32(uint32_t x, uint32_t r) {
#ifdef __CUDA_ARCH__
    return __funnelshift_l(x, x, r);
#else
    return (x << r) | (x >> (32u - r));
#endif
}

static __host__ __device__ __forceinline__ U2 threefry2x32(uint32_t k0, uint32_t k1,
                                                           uint32_t x0, uint32_t x1) {
    uint32_t k2 = k0 ^ k1 ^ 0x1BD11BDAu;
    x0 += k0; x1 += k1;
#define TF_R(r) { x0 += x1; x1 = rotl32(x1, r); x1 ^= x0; }
    TF_R(13) TF_R(15) TF_R(26) TF_R(6)   x0 += k1; x1 += k2 + 1u;
    TF_R(17) TF_R(29) TF_R(16) TF_R(24)  x0 += k2; x1 += k0 + 2u;
    TF_R(13) TF_R(15) TF_R(26) TF_R(6)   x0 += k0; x1 += k1 + 3u;
    TF_R(17) TF_R(29) TF_R(16) TF_R(24)  x0 += k1; x1 += k2 + 4u;
    TF_R(13) TF_R(15) TF_R(26) TF_R(6)   x0 += k2; x1 += k0 + 5u;
#undef TF_R
    U2 r; r.x = x0; r.y = x1; return r;
}

// keep (u < 0.9): exact integer form of  bitcast(0x3f800000|bits>>9)-1 < 0.9f
static __device__ __forceinline__ bool keep_90(uint32_t k0, uint32_t k1, uint32_t idx) {
    U2 o = threefry2x32(k0, k1, 0u, idx);
    return (((o.x ^ o.y) >> 9)) < 0x00733333u;
}

// ------------------------------ device scratch -----------------------------
// INVARIANT: g_cnt is all-zero at the start of every kernel_launch call.
// (Zero-initialized at module load; k_scan3 re-zeroes it after consuming it.)
__device__ int      g_cnt[NROWS_MAX];
__device__ int      g_rowptr[NROWS_MAX];
__device__ int      g_rowend[NROWS_MAX];
__device__ int      g_cursor[NROWS_MAX];
__device__ int      g_blk[128];
__device__ uint32_t g_keep[(NEDGE_MAX + 31) / 32];
__device__ int      g_eid[NEDGE_MAX];
__device__ Edge     g_edges[NEDGE_MAX];
__device__ float    g_egoA[(size_t)NROWS_MAX * 64];
__device__ float    g_egoB[(size_t)NROWS_MAX * 64];

// ------------------------------ CSR build ----------------------------------
__global__ void k_hist(const int* __restrict__ rows, int E,
                       uint32_t k0, uint32_t k1) {
    int e = blockIdx.x * blockDim.x + threadIdx.x;
    bool keep = (e < E) && keep_90(k0, k1, (uint32_t)e);
    uint32_t m = __ballot_sync(0xffffffffu, keep);
    if ((e & 31) == 0 && e < E) g_keep[e >> 5] = m;
    if (keep) atomicAdd(&g_cnt[rows[e]], 1);
}

// block-level exclusive scan (coalesced), block totals to g_blk
__global__ void __launch_bounds__(1024) k_scan1(int n) {
    __shared__ int warpsum[32];
    int i = blockIdx.x * 1024 + threadIdx.x;
    int lane = threadIdx.x & 31, wid = threadIdx.x >> 5;
    int c = (i < n) ? g_cnt[i] : 0;

    int v = c;
    #pragma unroll
    for (int o = 1; o < 32; o <<= 1) {
        int u = __shfl_up_sync(0xffffffffu, v, o);
        if (lane >= o) v += u;
    }
    if (lane == 31) warpsum[wid] = v;
    __syncthreads();
    if (wid == 0) {
        int w = warpsum[lane];
        #pragma unroll
        for (int o = 1; o < 32; o <<= 1) {
            int u = __shfl_up_sync(0xffffffffu, w, o);
            if (lane >= o) w += u;
        }
        warpsum[lane] = w;
    }
    __syncthreads();

    int excl = (v - c) + (wid > 0 ? warpsum[wid - 1] : 0);
    if (i < n) g_rowptr[i] = excl;                 // exclusive within block
    if (threadIdx.x == 0) g_blk[blockIdx.x] = warpsum[31];  // block total
}

// apply cross-block offsets (scan2 folded in: warp 0 sums prior block totals),
// write cursor/rowend, RE-ZERO g_cnt (maintains invariant).
__global__ void __launch_bounds__(1024) k_scan3(int n, int nb) {
    __shared__ int s_off;
    if (threadIdx.x < 32) {
        int lane = threadIdx.x;
        int acc = 0;
        for (int b = lane; b < nb; b += 32)
            if (b < (int)blockIdx.x) acc += g_blk[b];
        #pragma unroll
        for (int o = 16; o > 0; o >>= 1)
            acc += __shfl_down_sync(0xffffffffu, acc, o);
        if (lane == 0) s_off = acc;
    }
    __syncthreads();
    int i = blockIdx.x * 1024 + threadIdx.x;
    if (i >= n) return;
    int v = g_rowptr[i] + s_off;
    int c = g_cnt[i];
    g_rowptr[i] = v;
    g_cursor[i] = v;
    g_rowend[i] = v + c;
    g_cnt[i]    = 0;
}

__global__ void k_scatter(const int* __restrict__ rows, int E) {
    int e = blockIdx.x * blockDim.x + threadIdx.x;
    if (e >= E) return;
    if ((g_keep[e >> 5] >> (e & 31)) & 1u) {
        int p = atomicAdd(&g_cursor[rows[e]], 1);
        g_eid[p] = e;
    }
}

// deterministic ordering: sort each row's edge ids ascending, then materialize
__global__ void k_sortfill(const int* __restrict__ cols,
                           const float* __restrict__ vals, int n) {
    int r = blockIdx.x * blockDim.x + threadIdx.x;
    if (r >= n) return;
    int s = g_rowptr[r], t = g_rowend[r];
    for (int i = s + 1; i < t; i++) {
        int key = g_eid[i];
        int j = i - 1;
        while (j >= s && g_eid[j] > key) { g_eid[j + 1] = g_eid[j]; j--; }
        g_eid[j + 1] = key;
    }
    for (int i = s; i < t; i++) {
        int e = g_eid[i];
        Edge ed; ed.col = cols[e]; ed.val = vals[e] * (1.0f / 0.9f);
        g_edges[i] = ed;
    }
}

// ------------------------------ fused layer kernel -------------------------
__device__ __forceinline__ void fma4(float4& a, float v, const float4& x) {
    a.x = fmaf(v, x.x, a.x); a.y = fmaf(v, x.y, a.y);
    a.z = fmaf(v, x.z, a.z); a.w = fmaf(v, x.w, a.w);
}

#define LB_THREADS 256
#define LB_ROWS    64   // rows per block; 4 threads per row in SpMM phase

__global__ void __launch_bounds__(LB_THREADS, 5)
k_layer(int srcSel,                       // 0 = emb param, 1 = egoA, 2 = egoB
        const float4* __restrict__ embIn,
        int dstSel,                       // 1 = egoA, 2 = egoB
        const float* __restrict__ W, const float* __restrict__ b,
        float4* __restrict__ out4,        // out as float4, row stride 64
        int layer,
        uint32_t k0, uint32_t k1,
        int copyEmb, int n)
{
    __shared__ __align__(16) float4 Ws[64 * 16];
    __shared__ __align__(16) float  side[LB_ROWS][68];  // padded (17 float4)
    __shared__ __align__(16) float  bs[64];

    const float4* ego = (srcSel == 0) ? embIn
                       : (srcSel == 1) ? (const float4*)g_egoA : (const float4*)g_egoB;
    float4* egoOut = (dstSel == 1) ? (float4*)g_egoA : (float4*)g_egoB;

    int tid = threadIdx.x;

    const float4* W4 = (const float4*)W;
    for (int i = tid; i < 1024; i += LB_THREADS) Ws[i] = W4[i];
    if (tid < 16) ((float4*)bs)[tid] = ((const float4*)b)[tid];

    // ---- hoist dropout mask computation (index-only) so the ~16 ciphers of
    //      ALU work overlap the SpMM gather latency ---------------------------
    int cg = tid & 15;        // GEMM column group (cols cg*4 .. cg*4+3)
    int rq = tid >> 4;        // GEMM row quad (local rows rq*4 .. rq*4+3)
    int rbase = blockIdx.x * LB_ROWS + rq * 4;
    uint32_t dmask = 0;
    #pragma unroll
    for (int m = 0; m < 4; m++) {
        uint32_t base = (uint32_t)(rbase + m) * 64u + (uint32_t)cg * 4u;
        #pragma unroll
        for (int j = 0; j < 4; j++)
            if (keep_90(k0, k1, base + (uint32_t)j)) dmask |= 1u << (m * 4 + j);
    }

    // -------- SpMM phase: 4 threads per row, each owns 4 float4 slots ------
    int lr = tid >> 2;        // 0..63 local row
    int l4 = tid & 3;         // 0..3  quarter
    int r  = blockIdx.x * LB_ROWS + lr;

    float4 a0 = {0,0,0,0}, a1 = a0, a2 = a0, a3 = a0;
    if (r < n) {
        int e   = g_rowptr[r];
        int end = g_rowend[r];
        for (; e + 1 < end; e += 2) {
            Edge e0 = g_edges[e];
            Edge e1 = g_edges[e + 1];
            const float4* p0 = ego + ((size_t)e0.col << 4) + l4;
            const float4* p1 = ego + ((size_t)e1.col << 4) + l4;
            float4 x00 = __ldg(p0),     x01 = __ldg(p0 + 4),
                   x02 = __ldg(p0 + 8), x03 = __ldg(p0 + 12);
            float4 x10 = __ldg(p1),     x11 = __ldg(p1 + 4),
                   x12 = __ldg(p1 + 8), x13 = __ldg(p1 + 12);
            fma4(a0, e0.val, x00); fma4(a1, e0.val, x01);
            fma4(a2, e0.val, x02); fma4(a3, e0.val, x03);
            fma4(a0, e1.val, x10); fma4(a1, e1.val, x11);
            fma4(a2, e1.val, x12); fma4(a3, e1.val, x13);
        }
        if (e < end) {
            Edge e0 = g_edges[e];
            const float4* p0 = ego + ((size_t)e0.col << 4) + l4;
            fma4(a0, e0.val, __ldg(p0));     fma4(a1, e0.val, __ldg(p0 + 4));
            fma4(a2, e0.val, __ldg(p0 + 8)); fma4(a3, e0.val, __ldg(p0 + 12));
        }
    }
    {
        float4* sp = (float4*)(&side[lr][0]);
        sp[l4] = a0; sp[l4 + 4] = a1; sp[l4 + 8] = a2; sp[l4 + 12] = a3;
    }
    __syncthreads();

    // -------- GEMM phase: thread = 4 cols (cg) x 4 rows (rq) ----------------
    float4 h[4];
    float4 bb = ((const float4*)bs)[cg];
    #pragma unroll
    for (int m = 0; m < 4; m++) h[m] = bb;

    #pragma unroll 16
    for (int k = 0; k < 64; k++) {
        float4 w = Ws[k * 16 + cg];
        #pragma unroll
        for (int m = 0; m < 4; m++) {
            float s = side[rq * 4 + m][k];
            h[m].x = fmaf(s, w.x, h[m].x);
            h[m].y = fmaf(s, w.y, h[m].y);
            h[m].z = fmaf(s, w.z, h[m].z);
            h[m].w = fmaf(s, w.w, h[m].w);
        }
    }

    // -------- dropout (precomputed mask) + ego_next + row-norm + out --------
    #pragma unroll
    for (int m = 0; m < 4; m++) {
        int row = rbase + m;
        float4 hm = h[m];
        hm.x = (dmask >> (m * 4 + 0)) & 1u ? hm.x * (1.0f / 0.9f) : 0.0f;
        hm.y = (dmask >> (m * 4 + 1)) & 1u ? hm.y * (1.0f / 0.9f) : 0.0f;
        hm.z = (dmask >> (m * 4 + 2)) & 1u ? hm.z * (1.0f / 0.9f) : 0.0f;
        hm.w = (dmask >> (m * 4 + 3)) & 1u ? hm.w * (1.0f / 0.9f) : 0.0f;

        float ss = hm.x * hm.x + hm.y * hm.y + hm.z * hm.z + hm.w * hm.w;
        #pragma unroll
        for (int msk = 1; msk <= 8; msk <<= 1)
            ss += __shfl_xor_sync(0xffffffffu, ss, msk);

        float nrm  = sqrtf(ss);
        float invn = 1.0f / fmaxf(nrm, 1e-12f);

        if (row < n) {
            egoOut[(size_t)row * 16 + cg] = hm;
            float4 o;
            o.x = hm.x * invn; o.y = hm.y * invn;
            o.z = hm.z * invn; o.w = hm.w * invn;
            out4[(size_t)row * 64 + (size_t)(layer + 1) * 16 + cg] = o;
            if (copyEmb)
                out4[(size_t)row * 64 + cg] = embIn[(size_t)row * 16 + cg];
        }
    }
}

// ------------------------------ host entry ---------------------------------
extern "C" void kernel_launch(void* const* d_in, const int* in_sizes, int n_in,
                              void* d_out, int out_size) {
    const int*   rows = (const int*)d_in[0];
    const int*   cols = (const int*)d_in[1];
    const float* vals = (const float*)d_in[2];
    const float* emb  = (const float*)d_in[3];
    const float* W0   = (const float*)d_in[4];
    const float* b0   = (const float*)d_in[5];
    const float* W1   = (const float*)d_in[6];
    const float* b1   = (const float*)d_in[7];
    const float* W2   = (const float*)d_in[8];
    const float* b2   = (const float*)d_in[9];

    int E = in_sizes[0];
    int N = in_sizes[3] / 64;
    if (E > NEDGE_MAX) E = NEDGE_MAX;
    if (N > NROWS_MAX) N = NROWS_MAX;
    float* out = (float*)d_out;

    // subkeys of jax.random.key(42) -> split(.,4): [k_node, k0, k1, k2]
    U2 kn = threefry2x32(0u, 42u, 0u, 0u);
    U2 kA = threefry2x32(0u, 42u, 0u, 1u);
    U2 kB = threefry2x32(0u, 42u, 0u, 2u);
    U2 kC = threefry2x32(0u, 42u, 0u, 3u);

    int tb = 256;
    int nb = (N + 1023) / 1024;
    // launches: [0]hist [1]scan1 [2]scan3 [3]scatter <- ncu
    //           [4]sortfill [5]layer0 [6]layer1 [7]layer2
    k_hist    <<<(E + tb - 1) / tb, tb>>>(rows, E, kn.x, kn.y);
    k_scan1   <<<nb, 1024>>>(N);
    k_scan3   <<<nb, 1024>>>(N, nb);
    k_scatter <<<(E + tb - 1) / tb, tb>>>(rows, E);
    k_sortfill<<<(N + tb - 1) / tb, tb>>>(cols, vals, N);

    int gb = (N + LB_ROWS - 1) / LB_ROWS;
    k_layer<<<gb, LB_THREADS>>>(0, (const float4*)emb, 1, W0, b0,
                                (float4*)out, 0, kA.x, kA.y, 1, N);
    k_layer<<<gb, LB_THREADS>>>(1, (const float4*)emb, 2, W1, b1,
                                (float4*)out, 1, kB.x, kB.y, 0, N);
    k_layer<<<gb, LB_THREADS>>>(2, (const float4*)emb, 1, W2, b2,
                                (float4*)out, 2, kC.x, kC.y, 0, N);
}